// round 16
// baseline (speedup 1.0000x reference)
#include <cuda_runtime.h>

typedef unsigned int u32;
typedef unsigned long long u64;

#define TPB 256

// smem byte offsets (fp16 tiles)
#define XQ_OFF 0            // X -> attn-out -> proj-A: fp16 64 rows x 136 (272B stride)
#define QS_OFF 17408        // Q: fp16 64 x 136 (rows 49..63 garbage, masked downstream)
#define KS_OFF 34816        // K: fp16 56 x 136 (pad rows 49..55 zeroed)
#define VT_OFF 50048        // V^T: fp16 128 dims x 72 toks (144B stride; toks 48..63 words zeroed)
#define SMB    68480

// pre-packed fp16 B fragments: [phase q,k,v,proj][ntile 16][kstep 8 (k16)][lane 32] -> u64(b0,b1)
__device__ u64 g_B[4 * 4096];
// expanded rel-pos bias in S-fragment order: [cls=h2*2+msel][fidx=nt*2+mt][lane] -> float4
__device__ float4 g_bias4[8 * 14 * 32];

// pack two f32 -> f16x2 (lo = first arg)
__device__ __forceinline__ u32 pack_h2(float lo, float hi) {
    u32 d; asm("cvt.rn.f16x2.f32 %0, %1, %2;" : "=r"(d) : "f"(hi), "f"(lo)); return d;
}

__global__ void repack(const float* __restrict__ qw, const float* __restrict__ pw,
                       const float* __restrict__ bt)
{
    int i = blockIdx.x * 256 + threadIdx.x;
    if (i < 16384) {
        int phase = i >> 12;
        int rem   = i & 4095;
        int nt    = rem >> 8;
        int ks    = (rem >> 5) & 7;
        int lane  = rem & 31;
        int n  = nt * 8 + (lane >> 2);
        int k0 = ks * 16 + (lane & 3) * 2;
        float f00, f01, f10, f11;
        if (phase < 3) {
            f00 = qw[(k0    ) * 384 + phase * 128 + n];
            f01 = qw[(k0 + 1) * 384 + phase * 128 + n];
            f10 = qw[(k0 + 8) * 384 + phase * 128 + n];
            f11 = qw[(k0 + 9) * 384 + phase * 128 + n];
        } else {
            f00 = pw[(k0    ) * 128 + n];
            f01 = pw[(k0 + 1) * 128 + n];
            f10 = pw[(k0 + 8) * 128 + n];
            f11 = pw[(k0 + 9) * 128 + n];
        }
        u32 b0 = pack_h2(f00, f01), b1 = pack_h2(f10, f11);
        g_B[i] = ((u64)b1 << 32) | (u64)b0;
    } else if (i < 16384 + 3584) {
        int j4   = i - 16384;              // float4 index
        int cls  = j4 / 448;               // h2*2 + msel
        int rem  = j4 - cls * 448;
        int fidx = rem >> 5;               // nt*2 + mt
        int lane = rem & 31;
        int msel = cls & 1;
        int h2 = cls >> 1;
        int nt = fidx >> 1, mt = fidx & 1;
        float v4[4];
        #pragma unroll
        for (int v = 0; v < 4; v++) {
            int row = msel * 32 + mt * 16 + (lane >> 2) + ((v >> 1) ? 8 : 0);
            int col = nt * 8 + (lane & 3) * 2 + (v & 1);
            if (col >= 49) v4[v] = -1e30f;     // padded key col -> p = 0
            else {
                int r = min(row, 48);
                int iy = r / 7, ix = r - iy * 7, jy = col / 7, jx = col - jy * 7;
                v4[v] = bt[((iy - jy + 6) * 13 + (ix - jx + 6)) * 4 + h2];
            }
        }
        g_bias4[j4] = make_float4(v4[0], v4[1], v4[2], v4[3]);
    }
}

// ---------------- helpers ----------------
__device__ __forceinline__ u32 lds32(u32 a) {
    u32 v; asm volatile("ld.shared.b32 %0, [%1];" : "=r"(v) : "r"(a)); return v;
}
__device__ __forceinline__ void sts32(u32 a, u32 v) {
    asm volatile("st.shared.b32 [%0], %1;" :: "r"(a), "r"(v) : "memory");
}
__device__ __forceinline__ void sts16(u32 a, u32 v) {
    asm volatile("st.shared.u16 [%0], %1;" :: "r"(a), "r"(v) : "memory");
}
__device__ __forceinline__ void sts64u(u32 a, u32 x, u32 y) {
    asm volatile("st.shared.v2.b32 [%0], {%1,%2};" :: "r"(a), "r"(x), "r"(y) : "memory");
}
__device__ __forceinline__ void ldgB(u32& b0, u32& b1, const u64* p) {
    asm volatile("ld.global.nc.v2.u32 {%0,%1}, [%2];" : "=r"(b0), "=r"(b1) : "l"(p));
}
__device__ __forceinline__ void mma16(float c[4], const u32 a[4], u32 b0, u32 b1) {
    asm("mma.sync.aligned.m16n8k16.row.col.f32.f16.f16.f32 "
        "{%0,%1,%2,%3},{%4,%5,%6,%7},{%8,%9},{%0,%1,%2,%3};"
        : "+f"(c[0]), "+f"(c[1]), "+f"(c[2]), "+f"(c[3])
        : "r"(a[0]), "r"(a[1]), "r"(a[2]), "r"(a[3]), "r"(b0), "r"(b1));
}

// D[64x128] = A[64x128]·B ; A = fp16 smem tile, stride 272B; warp tile m32 x n32
__device__ __forceinline__ void gemm64h(u32 As_addr, const u64* __restrict__ Bp,
                                        int mrow, int ncol, int lane, float acc[2][4][4])
{
    const int lq = lane >> 2, lr = lane & 3;
    const int ncg = ncol >> 3;
    #pragma unroll
    for (int ks = 0; ks < 8; ks++) {
        u32 a[2][4];
        #pragma unroll
        for (int mt = 0; mt < 2; mt++) {
            u32 ap = As_addr + (u32)((mrow + mt * 16 + lq) * 272 + ks * 32 + lr * 4);
            a[mt][0] = lds32(ap);
            a[mt][1] = lds32(ap + 8 * 272);
            a[mt][2] = lds32(ap + 16);
            a[mt][3] = lds32(ap + 8 * 272 + 16);
        }
        u32 b0[4], b1[4];
        #pragma unroll
        for (int nt = 0; nt < 4; nt++)
            ldgB(b0[nt], b1[nt], Bp + (((ncg + nt) * 8 + ks) * 32 + lane));
        #pragma unroll
        for (int mt = 0; mt < 2; mt++)
            #pragma unroll
            for (int nt = 0; nt < 4; nt++)
                mma16(acc[mt][nt], a[mt], b0[nt], b1[nt]);
    }
}

// fused K/V/Q GEMM: one A-tile pass feeds 3 weight matrices (3 independent mma chains)
__device__ __forceinline__ void gemm64h_kvq(u32 As_addr, int mrow, int ncol, int lane,
                                            float acc[3][2][4][4])
{
    const int lq = lane >> 2, lr = lane & 3;
    const int ncg = ncol >> 3;
    #pragma unroll
    for (int ks = 0; ks < 8; ks++) {
        u32 a[2][4];
        #pragma unroll
        for (int mt = 0; mt < 2; mt++) {
            u32 ap = As_addr + (u32)((mrow + mt * 16 + lq) * 272 + ks * 32 + lr * 4);
            a[mt][0] = lds32(ap);
            a[mt][1] = lds32(ap + 8 * 272);
            a[mt][2] = lds32(ap + 16);
            a[mt][3] = lds32(ap + 8 * 272 + 16);
        }
        #pragma unroll
        for (int p = 0; p < 3; p++) {
            u32 b0[4], b1[4];
            #pragma unroll
            for (int nt = 0; nt < 4; nt++)
                ldgB(b0[nt], b1[nt], g_B + p * 4096 + (((ncg + nt) * 8 + ks) * 32 + lane));
            #pragma unroll
            for (int mt = 0; mt < 2; mt++)
                #pragma unroll
                for (int nt = 0; nt < 4; nt++)
                    mma16(acc[p][mt][nt], a[mt], b0[nt], b1[nt]);
        }
    }
}

// store K/Q tiles as fp16 row-major (stride 272B), rows < 49 only
__device__ __forceinline__ void store_rows_h(float acc[2][4][4], u32 dst_addr,
                                             const float* __restrict__ bias,
                                             int mrow, int ncol, int lane)
{
    const int lq = lane >> 2, lr = lane & 3;
    #pragma unroll
    for (int nt = 0; nt < 4; nt++) {
        const int c = ncol + nt * 8 + lr * 2;
        const float blo = __ldg(bias + c), bhi = __ldg(bias + c + 1);
        #pragma unroll
        for (int mt = 0; mt < 2; mt++) {
            const int r = mrow + mt * 16 + lq;
            if (r < 49)
                sts32(dst_addr + (u32)(r * 272 + c * 2),
                      pack_h2(acc[mt][nt][0] + blo, acc[mt][nt][1] + bhi));
            if (r + 8 < 49)
                sts32(dst_addr + (u32)((r + 8) * 272 + c * 2),
                      pack_h2(acc[mt][nt][2] + blo, acc[mt][nt][3] + bhi));
        }
    }
}

// store V transposed: VT[dim][token] fp16, stride 144B; row-pairs built via shfl_xor(4)
__device__ __forceinline__ void store_vT(float acc[2][4][4], u32 vt_addr,
                                         const float* __restrict__ bias,
                                         int mrow, int ncol, int lane)
{
    const int lq = lane >> 2, lr = lane & 3;
    const int odd = lq & 1;
    #pragma unroll
    for (int nt = 0; nt < 4; nt++) {
        const int c = ncol + nt * 8 + lr * 2;
        const float blo = __ldg(bias + c), bhi = __ldg(bias + c + 1);
        #pragma unroll
        for (int mt = 0; mt < 2; mt++) {
            #pragma unroll
            for (int half = 0; half < 2; half++) {
                const int r = mrow + mt * 16 + lq + half * 8;
                float v0 = acc[mt][nt][2 * half] + blo;
                float v1 = acc[mt][nt][2 * half + 1] + bhi;
                float o0 = __shfl_xor_sync(0xffffffffu, v0, 4);
                float o1 = __shfl_xor_sync(0xffffffffu, v1, 4);
                const int r0 = r & ~1;
                const int cc = c + odd;
                const u32 val = odd ? pack_h2(o1, v1) : pack_h2(v0, o0);
                const u32 addr = vt_addr + (u32)(cc * 144 + r0 * 2);
                if (r0 + 1 < 49)      sts32(addr, val);
                else if (r0 == 48)    sts16(addr, val);
            }
        }
    }
}

__global__ __launch_bounds__(TPB, 2)
void win_attn_kernel(const float* __restrict__ x,
                     const float* __restrict__ qkv_b,
                     const float* __restrict__ proj_b,
                     float* __restrict__ out)
{
    extern __shared__ char smem[];
    const u32 sbase = (u32)__cvta_generic_to_shared(smem);
    const u32 XQ_a = sbase + XQ_OFF;
    const u32 QS_a = sbase + QS_OFF;
    const u32 KS_a = sbase + KS_OFF;
    const u32 VT_a = sbase + VT_OFF;

    const int t    = threadIdx.x;
    const int wid  = t >> 5;
    const int lane = t & 31;
    const int lq   = lane >> 2, lr = lane & 3;
    const int mrow = (wid >> 2) * 32;
    const int ncol = (wid & 3) * 32;

    const int blk = blockIdx.x;
    const int b   = blk >> 6;
    const int win = blk & 63;
    const int wy  = win >> 3;
    const int wx  = win & 7;
    const long base = (((long)b * 56 + wy * 7) * 56 + wx * 7) * 128;

    // zero pads: K rows 49..55 (476 u32), VT tok-words 24..31 (toks 48..63; tok48 rewritten)
    for (int i = t; i < 476; i += TPB) {
        int rr = i / 68, cc = i - rr * 68;
        sts32(KS_a + (u32)((49 + rr) * 272 + cc * 4), 0u);
    }
    for (int i = t; i < 1024; i += TPB) {
        int d = i >> 3, wd = i & 7;
        sts32(VT_a + (u32)(d * 144 + (24 + wd) * 4), 0u);
    }

    // stage X (49x128) as fp16 into XQ
    for (int idx = t; idx < 49 * 32; idx += TPB) {
        int r  = idx >> 5;
        int c4 = idx & 31;
        int iy = r / 7, ix = r - iy * 7;
        const float4 v = *(const float4*)(x + base + ((long)iy * 56 + ix) * 128 + c4 * 4);
        sts64u(XQ_a + (u32)(r * 272 + c4 * 8),
               pack_h2(v.x, v.y), pack_h2(v.z, v.w));
    }
    __syncthreads();

    // ---- fused Q/K/V GEMM (single A-tile pass, 3 accumulator sets) ----
    {
        float acc[3][2][4][4];
        #pragma unroll
        for (int p = 0; p < 3; p++)
            #pragma unroll
            for (int a = 0; a < 2; a++)
                #pragma unroll
                for (int q = 0; q < 4; q++)
                    #pragma unroll
                    for (int c = 0; c < 4; c++) acc[p][a][q][c] = 0.f;
        gemm64h_kvq(XQ_a, mrow, ncol, lane, acc);
        store_rows_h(acc[1], KS_a, qkv_b + 128, mrow, ncol, lane);
        store_vT(acc[2], VT_a, qkv_b + 256, mrow, ncol, lane);
        store_rows_h(acc[0], QS_a, qkv_b, mrow, ncol, lane);   // own region: no WAR on X
    }
    __syncthreads();

    // ================= attention: warp = (head h2, m-half msel) =================
    const int h2   = wid >> 1;
    const int msel = wid & 1;
    const int mra  = msel * 32;
    const int cls  = wid;                                // h2*2 + msel
    const float scale = 0.17677669529663687f;            // 32^-0.5

    // ---- S = Q·K^T  (m32 x n56, K=32 -> 2 k16 steps); A from QS ----
    float sacc[2][7][4];
    #pragma unroll
    for (int a = 0; a < 2; a++) for (int q = 0; q < 7; q++) for (int c = 0; c < 4; c++) sacc[a][q][c] = 0.f;
    #pragma unroll
    for (int ks = 0; ks < 2; ks++) {
        u32 a[2][4];
        #pragma unroll
        for (int mt = 0; mt < 2; mt++) {
            u32 ap = QS_a + (u32)((mra + mt * 16 + lq) * 272 + h2 * 64 + ks * 32 + lr * 4);
            a[mt][0] = lds32(ap);
            a[mt][1] = lds32(ap + 8 * 272);
            a[mt][2] = lds32(ap + 16);
            a[mt][3] = lds32(ap + 8 * 272 + 16);
        }
        #pragma unroll
        for (int nt = 0; nt < 7; nt++) {
            u32 bp = KS_a + (u32)((nt * 8 + lq) * 272 + h2 * 64 + ks * 32 + lr * 4);
            u32 b0 = lds32(bp), b1 = lds32(bp + 16);
            mma16(sacc[0][nt], a[0], b0, b1);
            mma16(sacc[1][nt], a[1], b0, b1);
        }
    }

    // ---- softmax -> P·V A-fragments directly in registers ----
    u32 paf[2][4][4];
    paf[0][3][2] = paf[0][3][3] = paf[1][3][2] = paf[1][3][3] = 0u;   // cols 56..63 = 0
    float part[4] = {0.f, 0.f, 0.f, 0.f};
    #pragma unroll
    for (int nt = 0; nt < 7; nt++) {
        #pragma unroll
        for (int mt = 0; mt < 2; mt++) {
            const float4 gb = __ldg(g_bias4 + (cls * 14 + nt * 2 + mt) * 32 + lane);
            float p0 = __expf(fmaf(sacc[mt][nt][0], scale, gb.x));
            float p1 = __expf(fmaf(sacc[mt][nt][1], scale, gb.y));
            float p2 = __expf(fmaf(sacc[mt][nt][2], scale, gb.z));
            float p3 = __expf(fmaf(sacc[mt][nt][3], scale, gb.w));
            part[2 * mt]     += p0 + p1;
            part[2 * mt + 1] += p2 + p3;
            const int ks = nt >> 1;
            if ((nt & 1) == 0) {
                paf[mt][ks][0] = pack_h2(p0, p1);
                paf[mt][ks][1] = pack_h2(p2, p3);
            } else {
                paf[mt][ks][2] = pack_h2(p0, p1);
                paf[mt][ks][3] = pack_h2(p2, p3);
            }
        }
    }
    float inv[4];
    #pragma unroll
    for (int s = 0; s < 4; s++) {
        float l = part[s];
        l += __shfl_xor_sync(0xffffffffu, l, 1);
        l += __shfl_xor_sync(0xffffffffu, l, 2);
        inv[s] = 1.f / l;
    }

    // ---- O = P·V  (m32 x n32, K=64 -> 4 k16 steps; P from registers, VT is B) ----
    float oacc[2][4][4];
    #pragma unroll
    for (int a = 0; a < 2; a++) for (int q = 0; q < 4; q++) for (int c = 0; c < 4; c++) oacc[a][q][c] = 0.f;
    #pragma unroll
    for (int ks = 0; ks < 4; ks++) {
        #pragma unroll
        for (int nt = 0; nt < 4; nt++) {
            u32 bp = VT_a + (u32)((h2 * 32 + nt * 8 + lq) * 144 + ks * 32 + lr * 4);
            u32 b0 = lds32(bp), b1 = lds32(bp + 16);
            mma16(oacc[0][nt], paf[0][ks], b0, b1);
            mma16(oacc[1][nt], paf[1][ks], b0, b1);
        }
    }

    // ---- O epilogue: normalize -> fp16 into XQ (X dead; full tile rewritten) ----
    #pragma unroll
    for (int mt = 0; mt < 2; mt++) {
        #pragma unroll
        for (int nt = 0; nt < 4; nt++) {
            const int col = h2 * 32 + nt * 8 + 2 * lr;
            const u32 ra = XQ_a + (u32)((mra + mt * 16 + lq) * 272 + col * 2);
            sts32(ra, pack_h2(oacc[mt][nt][0] * inv[2 * mt],
                              oacc[mt][nt][1] * inv[2 * mt]));
            sts32(ra + 8 * 272, pack_h2(oacc[mt][nt][2] * inv[2 * mt + 1],
                                        oacc[mt][nt][3] * inv[2 * mt + 1]));
        }
    }
    __syncthreads();

    // ---- proj phase ----
    {
        float acc[2][4][4];
        #pragma unroll
        for (int a = 0; a < 2; a++) for (int q = 0; q < 4; q++) for (int c = 0; c < 4; c++) acc[a][q][c] = 0.f;
        gemm64h(XQ_a, g_B + 3 * 4096, mrow, ncol, lane, acc);

        #pragma unroll
        for (int nt = 0; nt < 4; nt++) {
            const int c = ncol + nt * 8 + lr * 2;
            const float blo = __ldg(proj_b + c), bhi = __ldg(proj_b + c + 1);
            #pragma unroll
            for (int mt = 0; mt < 2; mt++) {
                #pragma unroll
                for (int half = 0; half < 2; half++) {
                    const int r = mrow + mt * 16 + lq + half * 8;
                    if (r < 49) {
                        const int iy = r / 7, ix = r - iy * 7;
                        float2 v;
                        v.x = acc[mt][nt][2 * half + 0] + blo;
                        v.y = acc[mt][nt][2 * half + 1] + bhi;
                        *(float2*)(out + base + ((long)iy * 56 + ix) * 128 + c) = v;
                    }
                }
            }
        }
    }
}

extern "C" void kernel_launch(void* const* d_in, const int* in_sizes, int n_in,
                              void* d_out, int out_size)
{
    const float* x      = (const float*)d_in[0];
    const float* qkv_w  = (const float*)d_in[1];
    const float* qkv_b  = (const float*)d_in[2];
    const float* proj_w = (const float*)d_in[3];
    const float* proj_b = (const float*)d_in[4];
    const float* bt     = (const float*)d_in[5];
    float* out = (float*)d_out;

    repack<<<78, 256>>>(qkv_w, proj_w, bt);

    cudaFuncSetAttribute(win_attn_kernel,
                         cudaFuncAttributeMaxDynamicSharedMemorySize, SMB);
    win_attn_kernel<<<4096, TPB, SMB>>>(x, qkv_b, proj_b, out);
}